// round 1
// baseline (speedup 1.0000x reference)
#include <cuda_runtime.h>
#include <math.h>
#include <stdint.h>

// ---------------- problem constants (static per reference) ----------------
#define BSZ   8
#define NQ    4096
#define CDIM  256
#define NHEAD 8
#define NPT   4
#define NLVL  6
#define NVAL  10752
#define DHEAD 32          // CDIM / NHEAD
#define NOFF  384         // NHEAD*NLVL*NPT*2
#define NATT  192         // NHEAD*NLVL*NPT

// ---------------- device scratch (static, no allocation) ------------------
__device__ float g_vproj[(size_t)BSZ * NVAL * CDIM];  // value @ W_val + b_val
__device__ float g_off  [(size_t)BSZ * NQ   * NOFF];  // q @ W_off + b_off
__device__ float g_attn [(size_t)BSZ * NQ   * NATT];  // q @ W_attn + b_attn (pre-softmax)
__device__ float g_ms   [(size_t)BSZ * NQ   * CDIM];  // deform-attn output (head-major)

__constant__ int c_H[NLVL] = {64, 32, 16, 64, 32, 16};
__constant__ int c_W[NLVL] = {64, 32, 16, 64, 32, 16};
__constant__ int c_S[NLVL] = {0, 4096, 5120, 5376, 9472, 10496};

// ---------------- tiled fp32 GEMM: C[M,N] = (A (+A2)) @ B + bias (+resid) --
// BM=128, BN=64, BK=16, 256 threads, 8x4 micro-tile per thread.
// Requires M%128==0, N%64==0, K%16==0 (holds for all 4 GEMMs here).
template <bool ADD_A2, bool RESID>
__global__ __launch_bounds__(256)
void gemm_kernel(const float* __restrict__ A, const float* __restrict__ A2,
                 const float* __restrict__ B, const float* __restrict__ bias,
                 const float* __restrict__ resid, float* __restrict__ C,
                 int M, int N, int K)
{
    const int BM = 128, BN = 64, BK = 16;
    __shared__ float As[BK][BM];
    __shared__ float Bs[BK][BN];

    const int tid = threadIdx.x;
    const int bm = blockIdx.x * BM;
    const int bn = blockIdx.y * BN;
    const int ty = tid >> 4;          // 0..15 -> 8 rows each
    const int tx = tid & 15;          // 0..15 -> 4 cols each

    // global load indexing
    const int ar = tid >> 2;          // 0..63 (rows ar, ar+64)
    const int ac = (tid & 3) * 4;     // 0,4,8,12
    const int br = tid >> 4;          // 0..15
    const int bc = (tid & 15) * 4;    // 0..60

    float acc[8][4];
#pragma unroll
    for (int i = 0; i < 8; i++)
#pragma unroll
        for (int j = 0; j < 4; j++) acc[i][j] = 0.f;

    for (int k0 = 0; k0 < K; k0 += BK) {
#pragma unroll
        for (int rr = 0; rr < 2; rr++) {
            const int row = ar + rr * 64;
            float4 v = *(const float4*)(A + (size_t)(bm + row) * K + k0 + ac);
            if (ADD_A2) {
                float4 u = *(const float4*)(A2 + (size_t)(bm + row) * K + k0 + ac);
                v.x += u.x; v.y += u.y; v.z += u.z; v.w += u.w;
            }
            As[ac + 0][row] = v.x;
            As[ac + 1][row] = v.y;
            As[ac + 2][row] = v.z;
            As[ac + 3][row] = v.w;
        }
        *(float4*)(&Bs[br][bc]) =
            *(const float4*)(B + (size_t)(k0 + br) * N + bn + bc);
        __syncthreads();

#pragma unroll
        for (int k = 0; k < BK; k++) {
            float4 a0 = *(const float4*)(&As[k][ty * 8]);
            float4 a1 = *(const float4*)(&As[k][ty * 8 + 4]);
            float4 bb = *(const float4*)(&Bs[k][tx * 4]);
            float a[8] = {a0.x, a0.y, a0.z, a0.w, a1.x, a1.y, a1.z, a1.w};
            float b[4] = {bb.x, bb.y, bb.z, bb.w};
#pragma unroll
            for (int i = 0; i < 8; i++)
#pragma unroll
                for (int j = 0; j < 4; j++)
                    acc[i][j] = fmaf(a[i], b[j], acc[i][j]);
        }
        __syncthreads();
    }

    const float4 bv = *(const float4*)(bias + bn + tx * 4);
#pragma unroll
    for (int i = 0; i < 8; i++) {
        const int row = bm + ty * 8 + i;
        float4 o;
        o.x = acc[i][0] + bv.x;
        o.y = acc[i][1] + bv.y;
        o.z = acc[i][2] + bv.z;
        o.w = acc[i][3] + bv.w;
        if (RESID) {
            float4 r = *(const float4*)(resid + (size_t)row * N + bn + tx * 4);
            o.x += r.x; o.y += r.y; o.z += r.z; o.w += r.w;
        }
        *(float4*)(C + (size_t)row * N + bn + tx * 4) = o;
    }
}

// ---------------- sampling kernel: one warp per (b, q, head) ----------------
// Lanes 0..23 own one (level, point); warp-softmax over 24; then all 32 lanes
// cooperate on the 32-dim head vector: lane d accumulates dim d across the
// 24 points x 4 bilinear corners (indices/weights broadcast via shfl).
__global__ __launch_bounds__(256)
void sample_kernel(const float* __restrict__ refp, float* __restrict__ ms)
{
    const int warp = blockIdx.x * 8 + (threadIdx.x >> 5);
    const int lane = threadIdx.x & 31;
    // warp -> (b, q, h); NH=8 innermost
    const int h  = warp & 7;
    const int bq = warp >> 3;          // b*NQ + q
    const int b  = bq >> 12;           // NQ = 4096 = 2^12

    // ---- per-point prep (lanes 0..23) ----
    float a = -INFINITY;
    if (lane < 24) a = g_attn[(size_t)bq * NATT + h * 24 + lane];

    float m = a;
#pragma unroll
    for (int s = 16; s; s >>= 1) m = fmaxf(m, __shfl_xor_sync(0xffffffffu, m, s));
    float e = (lane < 24) ? __expf(a - m) : 0.f;
    float ssum = e;
#pragma unroll
    for (int s = 16; s; s >>= 1) ssum += __shfl_xor_sync(0xffffffffu, ssum, s);
    const float aw = e / ssum;

    int   i00 = 0, i01 = 0, i10 = 0, i11 = 0;
    float w00 = 0.f, w01 = 0.f, w10 = 0.f, w11 = 0.f;
    if (lane < 24) {
        const int l = lane >> 2;
        const int p = lane & 3;
        const int H = c_H[l], W = c_W[l], S = c_S[l];
        const size_t ob = (size_t)bq * NOFF + (((h * NLVL + l) * NPT + p) << 1);
        const float offx = g_off[ob + 0];
        const float offy = g_off[ob + 1];
        const size_t rb = ((size_t)bq * NLVL + l) << 1;
        const float rx = refp[rb + 0];
        const float ry = refp[rb + 1];
        // offset normalizer cancels: x = ref_x*W + off_x - 0.5
        const float x = rx * (float)W + offx - 0.5f;
        const float y = ry * (float)H + offy - 0.5f;
        const float xf = floorf(x), yf = floorf(y);
        const float lx = x - xf, ly = y - yf;
        const int ix = (int)xf, iy = (int)yf;
        const bool vx0 = (ix     >= 0) && (ix     < W);
        const bool vx1 = (ix + 1 >= 0) && (ix + 1 < W);
        const bool vy0 = (iy     >= 0) && (iy     < H);
        const bool vy1 = (iy + 1 >= 0) && (iy + 1 < H);
        const int cx0 = min(max(ix, 0), W - 1);
        const int cx1 = min(max(ix + 1, 0), W - 1);
        const int cy0 = min(max(iy, 0), H - 1);
        const int cy1 = min(max(iy + 1, 0), H - 1);
        i00 = S + cy0 * W + cx0;
        i01 = S + cy0 * W + cx1;
        i10 = S + cy1 * W + cx0;
        i11 = S + cy1 * W + cx1;
        w00 = aw * (1.f - lx) * (1.f - ly) * (float)(vx0 && vy0);
        w01 = aw * lx         * (1.f - ly) * (float)(vx1 && vy0);
        w10 = aw * (1.f - lx) * ly         * (float)(vx0 && vy1);
        w11 = aw * lx         * ly         * (float)(vx1 && vy1);
    }

    // ---- gather + accumulate: lane = head dim ----
    const float* __restrict__ vb =
        g_vproj + (size_t)b * NVAL * CDIM + h * DHEAD + lane;
    float acc0 = 0.f, acc1 = 0.f, acc2 = 0.f, acc3 = 0.f;
#pragma unroll
    for (int j = 0; j < 24; j++) {
        const int   p00 = __shfl_sync(0xffffffffu, i00, j);
        const int   p01 = __shfl_sync(0xffffffffu, i01, j);
        const int   p10 = __shfl_sync(0xffffffffu, i10, j);
        const int   p11 = __shfl_sync(0xffffffffu, i11, j);
        const float q00 = __shfl_sync(0xffffffffu, w00, j);
        const float q01 = __shfl_sync(0xffffffffu, w01, j);
        const float q10 = __shfl_sync(0xffffffffu, w10, j);
        const float q11 = __shfl_sync(0xffffffffu, w11, j);
        acc0 = fmaf(q00, __ldg(vb + (size_t)p00 * CDIM), acc0);
        acc1 = fmaf(q01, __ldg(vb + (size_t)p01 * CDIM), acc1);
        acc2 = fmaf(q10, __ldg(vb + (size_t)p10 * CDIM), acc2);
        acc3 = fmaf(q11, __ldg(vb + (size_t)p11 * CDIM), acc3);
    }
    ms[(size_t)bq * CDIM + h * DHEAD + lane] = (acc0 + acc1) + (acc2 + acc3);
}

// ---------------- launch ----------------
extern "C" void kernel_launch(void* const* d_in, const int* in_sizes, int n_in,
                              void* d_out, int out_size)
{
    const float* query  = (const float*)d_in[0];
    const float* qpos   = (const float*)d_in[1];
    const float* value  = (const float*)d_in[2];
    const float* refp   = (const float*)d_in[3];
    // d_in[4] = spatial_shapes (static, hardcoded)
    const float* W_off  = (const float*)d_in[5];
    const float* b_off  = (const float*)d_in[6];
    const float* W_attn = (const float*)d_in[7];
    const float* b_attn = (const float*)d_in[8];
    const float* W_val  = (const float*)d_in[9];
    const float* b_val  = (const float*)d_in[10];
    const float* W_out  = (const float*)d_in[11];
    const float* b_out  = (const float*)d_in[12];
    float* out = (float*)d_out;

    float *vproj, *offr, *attnr, *msb;
    cudaGetSymbolAddress((void**)&vproj, g_vproj);
    cudaGetSymbolAddress((void**)&offr,  g_off);
    cudaGetSymbolAddress((void**)&attnr, g_attn);
    cudaGetSymbolAddress((void**)&msb,   g_ms);

    const int MQ = BSZ * NQ;      // 32768
    const int MV = BSZ * NVAL;    // 86016

    // 1) value projection: [MV,256] @ [256,256] + b_val
    gemm_kernel<false, false><<<dim3(MV / 128, CDIM / 64), 256>>>(
        value, nullptr, W_val, b_val, nullptr, vproj, MV, CDIM, CDIM);

    // 2) offsets: (query+qpos) @ W_off + b_off  -> [MQ,384]
    gemm_kernel<true, false><<<dim3(MQ / 128, NOFF / 64), 256>>>(
        query, qpos, W_off, b_off, nullptr, offr, MQ, NOFF, CDIM);

    // 3) attention logits: (query+qpos) @ W_attn + b_attn -> [MQ,192]
    gemm_kernel<true, false><<<dim3(MQ / 128, NATT / 64), 256>>>(
        query, qpos, W_attn, b_attn, nullptr, attnr, MQ, NATT, CDIM);

    // 4) softmax + bilinear sampling -> g_ms [MQ,256]
    sample_kernel<<<(BSZ * NQ * NHEAD) / 8, 256>>>(refp, msb);

    // 5) output projection + residual: g_ms @ W_out + b_out + query
    gemm_kernel<false, true><<<dim3(MQ / 128, CDIM / 64), 256>>>(
        msb, nullptr, W_out, b_out, query, out, MQ, CDIM, CDIM);
}